// round 8
// baseline (speedup 1.0000x reference)
#include <cuda_runtime.h>

#define H      64
#define NSEG   1024
#define TPB    256
#define PCOLS  192
#define FULLM  0xffffffffu

// ---------------- scratch (no allocations allowed) ----------------
__device__ float g_seg_sum[NSEG];

// ---------------- helpers ----------------
__device__ __forceinline__ unsigned long long pk2(float x, float y) {
    unsigned long long r;
    asm("mov.b64 %0, {%1, %2};" : "=l"(r) : "f"(x), "f"(y));
    return r;
}
__device__ __forceinline__ unsigned long long add2(unsigned long long a,
                                                   unsigned long long b) {
    unsigned long long r;
    asm("add.rn.f32x2 %0, %1, %2;" : "=l"(r) : "l"(a), "l"(b));
    return r;
}
__device__ __forceinline__ unsigned long long fma2(unsigned long long a,
                                                   unsigned long long b,
                                                   unsigned long long c) {
    unsigned long long r;
    asm("fma.rn.f32x2 %0, %1, %2, %3;" : "=l"(r) : "l"(a), "l"(b), "l"(c));
    return r;
}

// ---------------- kernel 0: init ----------------
__global__ void init_kernel(float* __restrict__ out, int out_size) {
    int i = blockIdx.x * blockDim.x + threadIdx.x;
    if (i < out_size) out[i] = 0.0f;
    if (i < NSEG) g_seg_sum[i] = 0.0f;
}

// ---------------- kernel 1: warp-cooperative MLP + pooling ----------------
__global__ __launch_bounds__(TPB) void mega_kernel(
    const float* __restrict__ ht, const float* __restrict__ info,
    const float* __restrict__ fut, const int* __restrict__ seg,
    const float* __restrict__ w1, const float* __restrict__ b1,
    const float* __restrict__ w2, const float* __restrict__ b2,
    float* __restrict__ out, int M)
{
    const int tid = threadIdx.x;
    const int li  = tid & 31;
    const int wid = tid >> 5;
    const int wbase = blockIdx.x * TPB + wid * 32;

    // ---- per-thread fixed weights: 4 input columns x 16 hidden units ----
    // concat order: w1 rows 0..63 = ht cols, 64..127 = info cols.
    // lane li owns cols li*4..li*4+3 (li<16 -> ht cols, li>=16 -> info cols).
    const int col0 = li * 4;
    unsigned long long wreg[4][8];
#pragma unroll
    for (int c = 0; c < 4; c++) {
        const float4* wr = reinterpret_cast<const float4*>(w1 + (col0 + c) * 16);
#pragma unroll
        for (int q = 0; q < 4; q++) {
            float4 v = wr[q];
            wreg[c][2 * q]     = pk2(v.x, v.y);
            wreg[c][2 * q + 1] = pk2(v.z, v.w);
        }
    }
    // sum-scatter destination: lane li ends holding hidden unit myj
    const int myj = 8 * ((li >> 4) & 1) + 4 * ((li >> 3) & 1)
                  + 2 * ((li >> 2) & 1) + ((li >> 1) & 1);
    const float myb1 = b1[myj];
    const float myw2 = w2[myj];
    const float b2v  = b2[0];

    const int laneg = wbase + li;
    const int lanec = (laneg < M) ? laneg : (M - 1);
    const int segv  = seg[lanec];

    // lane li<16 reads ht cols [4li,4li+4); li>=16 reads info cols.
    const float* xbase = (li < 16) ? (ht + col0) : (info + (col0 - 64));
    const float2* fbase = reinterpret_cast<const float2*>(fut) + li;

    float ax0 = 0.f, ax1 = 0.f, ax2 = 0.f, ax3 = 0.f;   // ht/info col accums
    float af0 = 0.f, af1 = 0.f;                          // fut col accums
    float sumex = 0.f;
    int cur = __shfl_sync(FULLM, segv, 0);

    // prefetch row 0
    int rc0 = (wbase < M) ? wbase : (M - 1);
    float4 x4 = *reinterpret_cast<const float4*>(xbase + (size_t)rc0 * H);
    float2 f2 = fbase[(size_t)rc0 * (H / 2)];

#pragma unroll 4
    for (int r = 0; r < 32; r++) {
        // prefetch row r+1
        float4 nx4; float2 nf2;
        if (r < 31) {
            int rg = wbase + r + 1;
            int rc = (rg < M) ? rg : (M - 1);
            nx4 = *reinterpret_cast<const float4*>(xbase + (size_t)rc * H);
            nf2 = fbase[(size_t)rc * (H / 2)];
        }

        // ---- hidden partials: 8 packed f32x2 over this thread's 4 cols ----
        unsigned long long p[8];
#pragma unroll
        for (int k = 0; k < 8; k++) p[k] = 0ull;
#pragma unroll
        for (int c = 0; c < 4; c++) {
            float xc = (&x4.x)[c];
            unsigned long long xx = pk2(xc, xc);
#pragma unroll
            for (int k = 0; k < 8; k++)
                p[k] = fma2(xx, wreg[c][k], p[k]);
        }

        // ---- sum-scatter reduce over 32 lanes -> lane holds h[myj] ----
        {
            // L1: xor 16, keep upper 4 packs if bit4 set
            bool up = (li & 16);
            unsigned long long k0 = up ? p[4] : p[0], s0 = up ? p[0] : p[4];
            unsigned long long k1 = up ? p[5] : p[1], s1 = up ? p[1] : p[5];
            unsigned long long k2 = up ? p[6] : p[2], s2 = up ? p[2] : p[6];
            unsigned long long k3 = up ? p[7] : p[3], s3 = up ? p[3] : p[7];
            p[0] = add2(k0, __shfl_xor_sync(FULLM, s0, 16));
            p[1] = add2(k1, __shfl_xor_sync(FULLM, s1, 16));
            p[2] = add2(k2, __shfl_xor_sync(FULLM, s2, 16));
            p[3] = add2(k3, __shfl_xor_sync(FULLM, s3, 16));
        }
        {
            // L2: xor 8
            bool up = (li & 8);
            unsigned long long k0 = up ? p[2] : p[0], s0 = up ? p[0] : p[2];
            unsigned long long k1 = up ? p[3] : p[1], s1 = up ? p[1] : p[3];
            p[0] = add2(k0, __shfl_xor_sync(FULLM, s0, 8));
            p[1] = add2(k1, __shfl_xor_sync(FULLM, s1, 8));
        }
        {
            // L3: xor 4
            bool up = (li & 4);
            unsigned long long k0 = up ? p[1] : p[0], s0 = up ? p[0] : p[1];
            p[0] = add2(k0, __shfl_xor_sync(FULLM, s0, 4));
        }
        float h;
        {
            // L4: xor 2 (unpack pair), L5: xor 1 (fold duplicate halves)
            float lo, hi;
            asm("mov.b64 {%0, %1}, %2;" : "=f"(lo), "=f"(hi) : "l"(p[0]));
            bool up = (li & 2);
            float keep = up ? hi : lo;
            float send = up ? lo : hi;
            h = keep + __shfl_xor_sync(FULLM, send, 2);
            h += __shfl_xor_sync(FULLM, h, 1);
        }

        // ---- relu, w2 dot via butterfly (each j duplicated x2 -> *0.5) ----
        float scp = fmaxf(h + myb1, 0.0f) * myw2;
#pragma unroll
        for (int o = 16; o >= 1; o >>= 1)
            scp += __shfl_xor_sync(FULLM, scp, o);
        float score = 0.5f * scp + b2v;

        const int rowg = wbase + r;
        float ex = (rowg < M) ? __expf(score) : 0.0f;   // scores tiny: no max-shift

        // ---- segment flush (uniform branch, rare) ----
        int sr = __shfl_sync(FULLM, segv, r);
        if (sr != cur) {
            float* ob = &out[cur * PCOLS + col0];
            atomicAdd(ob + 0, ax0); atomicAdd(ob + 1, ax1);
            atomicAdd(ob + 2, ax2); atomicAdd(ob + 3, ax3);
            float* of = &out[cur * PCOLS + 128 + 2 * li];
            atomicAdd(of + 0, af0); atomicAdd(of + 1, af1);
            if (li == 0 && sumex != 0.f) atomicAdd(&g_seg_sum[cur], sumex);
            ax0 = ax1 = ax2 = ax3 = af0 = af1 = 0.f;
            sumex = 0.f;
            cur = sr;
        }

        // ---- pooling: reuse the MLP's input registers ----
        ax0 = fmaf(ex, x4.x, ax0); ax1 = fmaf(ex, x4.y, ax1);
        ax2 = fmaf(ex, x4.z, ax2); ax3 = fmaf(ex, x4.w, ax3);
        af0 = fmaf(ex, f2.x, af0); af1 = fmaf(ex, f2.y, af1);
        sumex += ex;

        x4 = nx4; f2 = nf2;
    }

    // final flush
    {
        float* ob = &out[cur * PCOLS + col0];
        atomicAdd(ob + 0, ax0); atomicAdd(ob + 1, ax1);
        atomicAdd(ob + 2, ax2); atomicAdd(ob + 3, ax3);
        float* of = &out[cur * PCOLS + 128 + 2 * li];
        atomicAdd(of + 0, af0); atomicAdd(of + 1, af1);
        if (li == 0 && sumex != 0.f) atomicAdd(&g_seg_sum[cur], sumex);
    }
}

// ---------------- kernel 2: normalize out by seg_sum ----------------
__global__ void normalize_kernel(float* __restrict__ out) {
    int i = blockIdx.x * blockDim.x + threadIdx.x;
    if (i < NSEG * PCOLS)
        out[i] /= g_seg_sum[i / PCOLS];
}

// ---------------- launch ----------------
extern "C" void kernel_launch(void* const* d_in, const int* in_sizes, int n_in,
                              void* d_out, int out_size)
{
    const float* ht   = (const float*)d_in[0];
    const float* info = (const float*)d_in[1];
    const float* fut  = (const float*)d_in[2];
    const int*   seg  = (const int*)  d_in[3];
    const float* w1   = (const float*)d_in[4];
    const float* b1   = (const float*)d_in[5];
    const float* w2   = (const float*)d_in[6];
    const float* b2   = (const float*)d_in[7];
    float* out = (float*)d_out;

    int M = in_sizes[0] / H;

    int init_n = out_size > NSEG ? out_size : NSEG;
    init_kernel<<<(init_n + 255) / 256, 256>>>(out, out_size);

    mega_kernel<<<(M + TPB - 1) / TPB, TPB>>>(ht, info, fut, seg,
                                              w1, b1, w2, b2, out, M);

    normalize_kernel<<<(NSEG * PCOLS + 255) / 256, 256>>>(out);
}

// round 9
// speedup vs baseline: 1.0907x; 1.0907x over previous
#include <cuda_runtime.h>
#include <cstdint>

#define H      64
#define NSEG   1024
#define TPB    128
#define WARPS  (TPB / 32)
#define ROWW   130               // padded words/row: 64 ht + 64 info + 2 pad
#define SLABW  (32 * ROWW)       // words per warp slab
#define PCOLS  192
#define FULLM  0xffffffffu

// ---------------- scratch (no allocations allowed) ----------------
__device__ float g_seg_sum[NSEG];

// ---------------- helpers ----------------
__device__ __forceinline__ unsigned long long pk2(float x, float y) {
    unsigned long long r;
    asm("mov.b64 %0, {%1, %2};" : "=l"(r) : "f"(x), "f"(y));
    return r;
}
__device__ __forceinline__ void fma2(unsigned long long& acc,
                                     unsigned long long a,
                                     unsigned long long b) {
    asm("fma.rn.f32x2 %0, %1, %2, %0;" : "+l"(acc) : "l"(a), "l"(b));
}
__device__ __forceinline__ void cpasync8(uint32_t dst, const void* src) {
    asm volatile("cp.async.ca.shared.global [%0], [%1], 8;"
                 :: "r"(dst), "l"(src));
}

// ---------------- kernel 0: init ----------------
__global__ void init_kernel(float* __restrict__ out, int out_size) {
    int i = blockIdx.x * blockDim.x + threadIdx.x;
    if (i < out_size) out[i] = 0.0f;
    if (i < NSEG) g_seg_sum[i] = 0.0f;
}

// ---------------- kernel 1: staged MLP + exp + seg-sum + pooling ------------
__global__ __launch_bounds__(TPB) void mega_kernel(
    const float* __restrict__ ht, const float* __restrict__ info,
    const float* __restrict__ fut, const int* __restrict__ seg,
    const float* __restrict__ w1, const float* __restrict__ b1,
    const float* __restrict__ w2, const float* __restrict__ b2,
    float* __restrict__ out, int M)
{
    extern __shared__ __align__(16) float dynsm[];   // WARPS * SLABW floats
    __shared__ __align__(16) float w1s[128 * 16];
    __shared__ __align__(16) float b1s[16];
    __shared__ __align__(16) float w2s[16];
    __shared__ float b2sv;

    const int tid = threadIdx.x;
    const int li  = tid & 31;
    const int wid = tid >> 5;
    const int wbase = blockIdx.x * TPB + wid * 32;

    for (int i = tid; i < 128 * 16; i += TPB) w1s[i] = w1[i];
    if (tid < 16) { b1s[tid] = b1[tid]; w2s[tid] = w2[tid]; }
    if (tid == 0) b2sv = b2[0];
    __syncthreads();

    float* slab = dynsm + wid * SLABW;
    const uint32_t slab_u32 =
        (uint32_t)__cvta_generic_to_shared(slab);

    // ---- stage 32 rows of ht+info into the warp slab (coalesced cp.async) --
    // step k copies row k: thread li moves float2 #li of ht and of info.
    {
#pragma unroll 8
        for (int k = 0; k < 32; k++) {
            int rg = wbase + k;
            int rc = (rg < M) ? rg : (M - 1);
            const float2* sh = reinterpret_cast<const float2*>(ht)
                             + (size_t)rc * (H / 2) + li;
            const float2* si = reinterpret_cast<const float2*>(info)
                             + (size_t)rc * (H / 2) + li;
            uint32_t d = slab_u32 + (uint32_t)(k * ROWW + 2 * li) * 4u;
            cpasync8(d, sh);
            cpasync8(d + 64 * 4, si);
        }
        asm volatile("cp.async.commit_group;" ::: "memory");
        asm volatile("cp.async.wait_group 0;" ::: "memory");
        __syncwarp();
    }

    const int laneg = wbase + li;
    const int lanec = (laneg < M) ? laneg : (M - 1);
    const int segv  = seg[lanec];

    // ---- phase 1: per-thread MLP on its own slab row (contiguous 128 cols) -
    unsigned long long hp[8];
#pragma unroll
    for (int q = 0; q < 8; q++)
        hp[q] = reinterpret_cast<const unsigned long long*>(b1s)[q];

    {
        const float2* xr = reinterpret_cast<const float2*>(slab + li * ROWW);
#pragma unroll
        for (int c2 = 0; c2 < 64; c2++) {
            float2 xv = xr[c2];
            unsigned long long x0 = pk2(xv.x, xv.x);
            unsigned long long x1 = pk2(xv.y, xv.y);
            const ulonglong2* w0 =
                reinterpret_cast<const ulonglong2*>(&w1s[(2 * c2) * 16]);
            const ulonglong2* w1p =
                reinterpret_cast<const ulonglong2*>(&w1s[(2 * c2 + 1) * 16]);
#pragma unroll
            for (int q = 0; q < 4; q++) {
                ulonglong2 wa = w0[q];
                ulonglong2 wb = w1p[q];
                fma2(hp[2 * q],     x0, wa.x);
                fma2(hp[2 * q + 1], x0, wa.y);
                fma2(hp[2 * q],     x1, wb.x);
                fma2(hp[2 * q + 1], x1, wb.y);
            }
        }
    }

    float sc = b2sv;
#pragma unroll
    for (int q = 0; q < 8; q++) {
        float lo, hi;
        asm("mov.b64 {%0, %1}, %2;" : "=f"(lo), "=f"(hi) : "l"(hp[q]));
        sc = fmaf(fmaxf(lo, 0.0f), w2s[2 * q + 0], sc);
        sc = fmaf(fmaxf(hi, 0.0f), w2s[2 * q + 1], sc);
    }
    const float ex = (laneg < M) ? __expf(sc) : 0.0f;   // scores tiny: no max-shift

    // ---- per-segment sum of ex (sorted ids -> warp-segmented reduce) ----
    {
        float v = ex;
#pragma unroll
        for (int o = 1; o < 32; o <<= 1) {
            float u  = __shfl_down_sync(FULLM, v, o);
            int   s2 = __shfl_down_sync(FULLM, segv, o);
            if (li + o < 32 && s2 == segv) v += u;
        }
        int sp = __shfl_up_sync(FULLM, segv, 1);
        if ((li == 0 || sp != segv) && v != 0.0f)
            atomicAdd(&g_seg_sum[segv], v);
    }

    // ---- phase 2: warp-local pooling; ht/info from slab, fut from global ---
    const float2* futp = reinterpret_cast<const float2*>(fut) + li;
    const int sp1 = __shfl_up_sync(FULLM, segv, 1);
    unsigned bmask = __ballot_sync(FULLM, li > 0 && sp1 != segv);
    const bool full_warp = (wbase + 32 <= M);

    float a0 = 0.f, a1 = 0.f, a2 = 0.f, a3 = 0.f, a4 = 0.f, a5 = 0.f;

    if (bmask == 0 && full_warp) {
        // fast path: whole warp one segment
#pragma unroll
        for (int r = 0; r < 32; r += 4) {
            float2 f0 = futp[(size_t)(wbase + r    ) * (H / 2)];
            float2 f1 = futp[(size_t)(wbase + r + 1) * (H / 2)];
            float2 f2 = futp[(size_t)(wbase + r + 2) * (H / 2)];
            float2 f3 = futp[(size_t)(wbase + r + 3) * (H / 2)];
            float p0 = __shfl_sync(FULLM, ex, r + 0);
            float p1 = __shfl_sync(FULLM, ex, r + 1);
            float p2 = __shfl_sync(FULLM, ex, r + 2);
            float p3 = __shfl_sync(FULLM, ex, r + 3);
#pragma unroll
            for (int u = 0; u < 4; u++) {
                float p = (u == 0) ? p0 : (u == 1) ? p1 : (u == 2) ? p2 : p3;
                const float* rw = slab + (r + u) * ROWW;
                float2 hv = *reinterpret_cast<const float2*>(rw + 2 * li);
                float2 iv = *reinterpret_cast<const float2*>(rw + 64 + 2 * li);
                a0 = fmaf(p, hv.x, a0); a1 = fmaf(p, hv.y, a1);
                a2 = fmaf(p, iv.x, a2); a3 = fmaf(p, iv.y, a3);
            }
            a4 = fmaf(p0, f0.x, a4); a5 = fmaf(p0, f0.y, a5);
            a4 = fmaf(p1, f1.x, a4); a5 = fmaf(p1, f1.y, a5);
            a4 = fmaf(p2, f2.x, a4); a5 = fmaf(p2, f2.y, a5);
            a4 = fmaf(p3, f3.x, a4); a5 = fmaf(p3, f3.y, a5);
        }
        const int s0 = __shfl_sync(FULLM, segv, 0);
        float* ob = &out[s0 * PCOLS + 2 * li];
        atomicAdd(ob,       a0); atomicAdd(ob + 1,   a1);
        atomicAdd(ob + 64,  a2); atomicAdd(ob + 65,  a3);
        atomicAdd(ob + 128, a4); atomicAdd(ob + 129, a5);
    } else {
        // slow path: boundary inside warp and/or partial tail warp
        int cur = __shfl_sync(FULLM, segv, 0);
        for (int r = 0; r < 32; r++) {
            int gr = wbase + r;
            if (gr >= M) break;                       // uniform across warp
            int   sr = __shfl_sync(FULLM, segv, r);
            float p  = __shfl_sync(FULLM, ex, r);
            if (sr != cur) {
                float* ob = &out[cur * PCOLS + 2 * li];
                atomicAdd(ob,       a0); atomicAdd(ob + 1,   a1);
                atomicAdd(ob + 64,  a2); atomicAdd(ob + 65,  a3);
                atomicAdd(ob + 128, a4); atomicAdd(ob + 129, a5);
                a0 = a1 = a2 = a3 = a4 = a5 = 0.f;
                cur = sr;
            }
            const float* rw = slab + r * ROWW;
            float2 hv = *reinterpret_cast<const float2*>(rw + 2 * li);
            float2 iv = *reinterpret_cast<const float2*>(rw + 64 + 2 * li);
            float2 fv = futp[(size_t)gr * (H / 2)];
            a0 = fmaf(p, hv.x, a0); a1 = fmaf(p, hv.y, a1);
            a2 = fmaf(p, iv.x, a2); a3 = fmaf(p, iv.y, a3);
            a4 = fmaf(p, fv.x, a4); a5 = fmaf(p, fv.y, a5);
        }
        float* ob = &out[cur * PCOLS + 2 * li];
        atomicAdd(ob,       a0); atomicAdd(ob + 1,   a1);
        atomicAdd(ob + 64,  a2); atomicAdd(ob + 65,  a3);
        atomicAdd(ob + 128, a4); atomicAdd(ob + 129, a5);
    }
}

// ---------------- kernel 2: normalize out by seg_sum ----------------
__global__ void normalize_kernel(float* __restrict__ out) {
    int i = blockIdx.x * blockDim.x + threadIdx.x;
    if (i < NSEG * PCOLS)
        out[i] /= g_seg_sum[i / PCOLS];
}

// ---------------- launch ----------------
extern "C" void kernel_launch(void* const* d_in, const int* in_sizes, int n_in,
                              void* d_out, int out_size)
{
    const float* ht   = (const float*)d_in[0];
    const float* info = (const float*)d_in[1];
    const float* fut  = (const float*)d_in[2];
    const int*   seg  = (const int*)  d_in[3];
    const float* w1   = (const float*)d_in[4];
    const float* b1   = (const float*)d_in[5];
    const float* w2   = (const float*)d_in[6];
    const float* b2   = (const float*)d_in[7];
    float* out = (float*)d_out;

    int M = in_sizes[0] / H;
    const int dyn = WARPS * SLABW * 4;   // 66,560 bytes

    cudaFuncSetAttribute(mega_kernel,
                         cudaFuncAttributeMaxDynamicSharedMemorySize, dyn);

    int init_n = out_size > NSEG ? out_size : NSEG;
    init_kernel<<<(init_n + 255) / 256, 256>>>(out, out_size);

    mega_kernel<<<(M + TPB - 1) / TPB, TPB, dyn>>>(ht, info, fut, seg,
                                                   w1, b1, w2, b2, out, M);

    normalize_kernel<<<(NSEG * PCOLS + 255) / 256, 256>>>(out);
}

// round 10
// speedup vs baseline: 1.3077x; 1.1989x over previous
#include <cuda_runtime.h>

#define H      64
#define NSEG   1024
#define TPB    256
#define PCOLS  192
#define FULLM  0xffffffffu

// ---------------- scratch (no allocations allowed; zero-init at load) -------
__device__ float g_out[NSEG * PCOLS];
__device__ float g_seg_sum[NSEG];

// ---------------- kernel 1: MLP + exp + seg-sum + warp-local pooling --------
__global__ __launch_bounds__(TPB, 5) void mega_kernel(
    const float* __restrict__ ht, const float* __restrict__ info,
    const float* __restrict__ fut, const int* __restrict__ seg,
    const float* __restrict__ w1, const float* __restrict__ b1,
    const float* __restrict__ w2, const float* __restrict__ b2, int M)
{
    __shared__ __align__(16) float w1s[128 * 16];
    __shared__ __align__(16) float b1s[16];
    __shared__ __align__(16) float w2s[16];
    __shared__ float b2sv;

    const int tid = threadIdx.x;
    const int li  = tid & 31;
    const int wid = tid >> 5;

    for (int i = tid; i < 128 * 16; i += TPB) w1s[i] = w1[i];
    if (tid < 16) { b1s[tid] = b1[tid]; w2s[tid] = w2[tid]; }
    if (tid == 0) b2sv = b2[0];
    __syncthreads();

    const int lane0 = blockIdx.x * TPB + tid;
    const int lane  = (lane0 < M) ? lane0 : (M - 1);   // clamp: OOB dup last row

    // ---- phase 1: per-thread MLP (packed f32x2 accumulators) ----
    unsigned long long hp[8];
#pragma unroll
    for (int q = 0; q < 8; q++)
        hp[q] = reinterpret_cast<const unsigned long long*>(b1s)[q];

#pragma unroll
    for (int half = 0; half < 2; half++) {
        const float4* x4 = reinterpret_cast<const float4*>(half ? info : ht)
                         + (size_t)lane * (H / 4);
#pragma unroll
        for (int kk = 0; kk < H / 4; kk++) {
            float4 xv = x4[kk];
            const int kbase = half * H + kk * 4;
#pragma unroll
            for (int c = 0; c < 4; c++) {
                float x = (&xv.x)[c];
                unsigned long long xx;
                asm("mov.b64 %0, {%1, %1};" : "=l"(xx) : "f"(x));
                const unsigned long long* wr =
                    reinterpret_cast<const unsigned long long*>(&w1s[(kbase + c) * 16]);
#pragma unroll
                for (int q = 0; q < 8; q++)
                    asm("fma.rn.f32x2 %0, %1, %2, %0;"
                        : "+l"(hp[q]) : "l"(xx), "l"(wr[q]));
            }
        }
    }
    float sc = b2sv;
#pragma unroll
    for (int q = 0; q < 8; q++) {
        float lo, hi;
        asm("mov.b64 {%0, %1}, %2;" : "=f"(lo), "=f"(hi) : "l"(hp[q]));
        sc = fmaf(fmaxf(lo, 0.0f), w2s[2 * q + 0], sc);
        sc = fmaf(fmaxf(hi, 0.0f), w2s[2 * q + 1], sc);
    }

    const int s = seg[lane];
    const float ex = (lane0 < M) ? __expf(sc) : 0.0f;   // scores tiny: no max-shift

    // ---- per-segment sum of ex (sorted ids -> warp-segmented reduce) ----
    {
        float v = ex;
#pragma unroll
        for (int o = 1; o < 32; o <<= 1) {
            float u  = __shfl_down_sync(FULLM, v, o);
            int   s2 = __shfl_down_sync(FULLM, s, o);
            if (li + o < 32 && s2 == s) v += u;
        }
        int sp = __shfl_up_sync(FULLM, s, 1);
        if ((li == 0 || sp != s) && v != 0.0f)
            atomicAdd(&g_seg_sum[s], v);
    }

    // ---- phase 2: warp-local pooling of this warp's 32 lanes ----
    const int wbase = blockIdx.x * TPB + wid * 32;
    const float2* hta = reinterpret_cast<const float2*>(ht)   + li;
    const float2* ina = reinterpret_cast<const float2*>(info) + li;
    const float2* fta = reinterpret_cast<const float2*>(fut)  + li;

    const int sp1 = __shfl_up_sync(FULLM, s, 1);
    unsigned bmask = __ballot_sync(FULLM, li > 0 && sp1 != s);
    const bool full_warp = (wbase + 32 <= M);

    float a0 = 0.f, a1 = 0.f, a2 = 0.f, a3 = 0.f, a4 = 0.f, a5 = 0.f;

    if (bmask == 0 && full_warp) {
        // fast path: one segment covers the whole warp (2-row batches)
#pragma unroll
        for (int r = 0; r < 32; r += 2) {
            size_t g0 = (size_t)(wbase + r) * (H / 2);
            float2 h0 = hta[g0], h1 = hta[g0 + 32];
            float2 i0 = ina[g0], i1 = ina[g0 + 32];
            float2 f0 = fta[g0], f1 = fta[g0 + 32];
            float p0 = __shfl_sync(FULLM, ex, r + 0);
            float p1 = __shfl_sync(FULLM, ex, r + 1);
            a0 = fmaf(p0, h0.x, a0); a1 = fmaf(p0, h0.y, a1);
            a2 = fmaf(p0, i0.x, a2); a3 = fmaf(p0, i0.y, a3);
            a4 = fmaf(p0, f0.x, a4); a5 = fmaf(p0, f0.y, a5);
            a0 = fmaf(p1, h1.x, a0); a1 = fmaf(p1, h1.y, a1);
            a2 = fmaf(p1, i1.x, a2); a3 = fmaf(p1, i1.y, a3);
            a4 = fmaf(p1, f1.x, a4); a5 = fmaf(p1, f1.y, a5);
        }
        const int s0 = __shfl_sync(FULLM, s, 0);
        float* ob = &g_out[s0 * PCOLS + 2 * li];
        atomicAdd(ob,       a0); atomicAdd(ob + 1,   a1);
        atomicAdd(ob + 64,  a2); atomicAdd(ob + 65,  a3);
        atomicAdd(ob + 128, a4); atomicAdd(ob + 129, a5);
    } else {
        // slow path: segment boundary inside warp and/or partial tail warp
        int cur = __shfl_sync(FULLM, s, 0);
        for (int r = 0; r < 32; r++) {
            int gr = wbase + r;
            if (gr >= M) break;                       // uniform across warp
            int   sr = __shfl_sync(FULLM, s,  r);
            float p  = __shfl_sync(FULLM, ex, r);
            if (sr != cur) {
                float* ob = &g_out[cur * PCOLS + 2 * li];
                atomicAdd(ob,       a0); atomicAdd(ob + 1,   a1);
                atomicAdd(ob + 64,  a2); atomicAdd(ob + 65,  a3);
                atomicAdd(ob + 128, a4); atomicAdd(ob + 129, a5);
                a0 = a1 = a2 = a3 = a4 = a5 = 0.f;
                cur = sr;
            }
            size_t g0 = (size_t)gr * (H / 2);
            float2 h = hta[g0], iv = ina[g0], f = fta[g0];
            a0 = fmaf(p, h.x,  a0); a1 = fmaf(p, h.y,  a1);
            a2 = fmaf(p, iv.x, a2); a3 = fmaf(p, iv.y, a3);
            a4 = fmaf(p, f.x,  a4); a5 = fmaf(p, f.y,  a5);
        }
        float* ob = &g_out[cur * PCOLS + 2 * li];
        atomicAdd(ob,       a0); atomicAdd(ob + 1,   a1);
        atomicAdd(ob + 64,  a2); atomicAdd(ob + 65,  a3);
        atomicAdd(ob + 128, a4); atomicAdd(ob + 129, a5);
    }
}

// ---------------- kernel 2: finalize (normalize + rezero scratch) -----------
// block b owns segment b: writes out[b,:], zeroes g_out[b,:] and g_seg_sum[b].
__global__ __launch_bounds__(PCOLS) void finalize_kernel(float* __restrict__ out) {
    const int b = blockIdx.x;
    const int j = threadIdx.x;
    const float s = g_seg_sum[b];
    const int idx = b * PCOLS + j;
    out[idx] = g_out[idx] / s;
    g_out[idx] = 0.0f;
    __syncthreads();
    if (j == 0) g_seg_sum[b] = 0.0f;
}

// ---------------- launch ----------------
extern "C" void kernel_launch(void* const* d_in, const int* in_sizes, int n_in,
                              void* d_out, int out_size)
{
    const float* ht   = (const float*)d_in[0];
    const float* info = (const float*)d_in[1];
    const float* fut  = (const float*)d_in[2];
    const int*   seg  = (const int*)  d_in[3];
    const float* w1   = (const float*)d_in[4];
    const float* b1   = (const float*)d_in[5];
    const float* w2   = (const float*)d_in[6];
    const float* b2   = (const float*)d_in[7];
    float* out = (float*)d_out;

    int M = in_sizes[0] / H;

    mega_kernel<<<(M + TPB - 1) / TPB, TPB>>>(ht, info, fut, seg,
                                              w1, b1, w2, b2, M);

    finalize_kernel<<<NSEG, PCOLS>>>(out);
}